// round 10
// baseline (speedup 1.0000x reference)
#include <cuda_runtime.h>
#include <cuda_fp16.h>
#include <math.h>
#include <stdint.h>

#define MAXN 50000
#define MAXE 800000

// ---------------- device scratch (no allocations allowed) ----------------
__device__ float g_G   [MAXN * 512];     // [rsum(C)|zsum(C)|in(C)|hn(C)] fp32, stride 4C
__device__ float g_POOL[256 * 128];
__device__ float g_FC1 [256 * 256];
__device__ float g_FC1T[128 * 256];
__device__ float g_BB  [896];            // combined bias per layer [4C]
__device__ int   g_src[MAXE];
__device__ int   g_dst[MAXE];
__device__ int   g_sse[MAXE];
__device__ int   g_cnt[MAXN];
__device__ int   g_off[MAXN + 1];
__device__ int   g_b32[MAXN];
__device__ int   g_flags[2];

// interleaved (hi,lo) fp16 buffers; AX rows = [aggx(C) | x(C)], stride 2C
__device__ __align__(16) __half2 g_AX[MAXN * 256];
__device__ __align__(16) __half2 g_AY[MAXN * 256];
__device__ __align__(16) __half2 g_BC[688128];   // combined B [4C,2C] x4 iters x3 layers

// ---------------- detect dtypes + zero CSR counters ----------------
__global__ void detect_kernel(const unsigned* __restrict__ ei,
                              const unsigned* __restrict__ bat, int E, int N) {
    int i = blockIdx.x * blockDim.x + threadIdx.x;
    if (i < N) g_cnt[i] = 0;
    if (blockIdx.x == 0 && threadIdx.x == 0) {
        int e64 = 1;
        for (int k = 0; k < 64; k++)
            if (ei[2 * k + 1] != 0u) { e64 = 0; break; }
        int b64 = 1;
        int b0 = N / 2 - 64;
        for (int k = 0; k < 64; k++)
            if (bat[2 * (b0 + k) + 1] != 0u) { b64 = 0; break; }
        g_flags[0] = e64;
        g_flags[1] = b64;
    }
}

__global__ void convert_idx(const void* __restrict__ ei, const void* __restrict__ bat,
                            int E, int N) {
    int i = blockIdx.x * blockDim.x + threadIdx.x;
    if (i < N)
        g_b32[i] = g_flags[1] ? (int)((const long long*)bat)[i] : ((const int*)bat)[i];
    if (i < E) {
        int s, d;
        if (g_flags[0]) {
            const long long* p = (const long long*)ei;
            s = (int)p[i]; d = (int)p[E + i];
        } else {
            const int* p = (const int*)ei;
            s = p[i]; d = p[E + i];
        }
        g_src[i] = s;
        g_dst[i] = d;
        atomicAdd(&g_cnt[d], 1);
    }
}

// ---------------- single-block exclusive scan ----------------
__global__ void __launch_bounds__(1024) scan_kernel(int N) {
    __shared__ int wsum[32];
    __shared__ int carry;
    const int tid = threadIdx.x, lane = tid & 31, wid = tid >> 5;
    if (tid == 0) carry = 0;
    __syncthreads();
    for (int base = 0; base < N; base += 1024) {
        int i = base + tid;
        int v = (i < N) ? g_cnt[i] : 0;
        int s = v;
#pragma unroll
        for (int o = 1; o < 32; o <<= 1) {
            int t = __shfl_up_sync(0xffffffffu, s, o);
            if (lane >= o) s += t;
        }
        if (lane == 31) wsum[wid] = s;
        __syncthreads();
        if (wid == 0) {
            int w = wsum[lane];
#pragma unroll
            for (int o = 1; o < 32; o <<= 1) {
                int t = __shfl_up_sync(0xffffffffu, w, o);
                if (lane >= o) w += t;
            }
            wsum[lane] = w;
        }
        __syncthreads();
        int excl = carry + ((wid > 0) ? wsum[wid - 1] : 0) + s - v;
        if (i < N) { g_off[i] = excl; g_cnt[i] = excl; }
        __syncthreads();
        if (tid == 0) carry += wsum[31];
        __syncthreads();
    }
    if (tid == 0) g_off[N] = carry;
}

__global__ void place_kernel(int E) {
    int i = blockIdx.x * blockDim.x + threadIdx.x;
    if (i >= E) return;
    int pos = atomicAdd(&g_cnt[g_dst[i]], 1);
    g_sse[pos] = g_src[i];
}

// ---------------- fp16 split helpers ----------------
__device__ __forceinline__ __half2 split_hl(float v) {
    __half h = __float2half_rn(v);
    __half l = __float2half_rn(v - __half2float(h));
    return __halves2half2(h, l);
}
__device__ __forceinline__ float join_hl(__half2 p) {
    float2 f = __half22float2(p);
    return f.x + f.y;
}
__device__ __forceinline__ float join_u(uint32_t u) {
    return join_hl(*(__half2*)&u);
}

// ---------------- merged weight prep ----------------
// Combined B[o,k] (output col o in [0,4C), k in [0,2C)):
//   o<2C :  k<C: Wc[o,k]          k>=C: whh[o, k-C]       bias bih[o]+bhh[o]
//   o<3C :  k<C: Wc[o,k]          k>=C: 0                 bias bih[o]
//   else :  k<C: 0                k>=C: whh[o-C, k-C]     bias bhh[o-C]
// with Wc[j,k] = sum_kk wih[j,kk] * W[it][k,kk]
struct PrepArgs {
    const float* W[3]; const float* whh[3]; const float* wih[3];
    const float* bih[3]; const float* bhh[3];
    __half2* bc[3]; float* bb[3];
    const float* fc1W; float* fc1T;
    const float* x; __half2* ax; int N;
};

__global__ void prep_all(PrepArgs a) {
    long long stride = (long long)gridDim.x * blockDim.x;
    long long t0 = (long long)blockIdx.x * blockDim.x + threadIdx.x;
#pragma unroll
    for (int L = 0; L < 3; L++) {
        const int C = (L == 0) ? 32 : (L == 1) ? 64 : 128;
        const int C2 = 2 * C, C3 = 3 * C, C4 = 4 * C;
        long long tot = 4LL * C4 * C2;
        for (long long idx = t0; idx < tot; idx += stride) {
            int it = (int)(idx / (C4 * C2));
            int rem = (int)(idx % (C4 * C2));
            int o = rem / C2, k = rem % C2;
            float v = 0.f;
            if (k < C) {
                if (o < C3) {
                    const float* wr = a.wih[L] + (size_t)o * C;
                    const float* Wr = a.W[L] + (size_t)it * C * C + (size_t)k * C;
                    float s = 0.f;
                    for (int kk = 0; kk < C; kk++) s += wr[kk] * Wr[kk];
                    v = s;
                }
            } else {
                if (o < C2)      v = a.whh[L][(size_t)o * C + (k - C)];
                else if (o >= C3) v = a.whh[L][(size_t)(o - C) * C + (k - C)];
            }
            a.bc[L][idx] = split_hl(v);
        }
        for (long long idx = t0; idx < C4; idx += stride) {
            int o = (int)idx;
            float v;
            if (o < C2)      v = a.bih[L][o] + a.bhh[L][o];
            else if (o < C3) v = a.bih[L][o];
            else             v = a.bhh[L][o - C];
            a.bb[L][idx] = v;
        }
    }
    for (long long idx = t0; idx < 128 * 256; idx += stride) {
        int k = (int)(idx / 256), j = (int)(idx % 256);
        a.fc1T[idx] = a.fc1W[(size_t)j * 128 + k];
    }
    // initial x -> AX cols [32,64), stride 64 (layer 0)
    long long totx = (long long)a.N * 32;
    for (long long idx = t0; idx < totx; idx += stride) {
        int n = (int)(idx / 32), k = (int)(idx % 32);
        a.ax[(size_t)n * 64 + 32 + k] = split_hl(a.x[idx]);
    }
}

// ================= smem-staged fp16x3 HMMA GEMM (interleaved, K-chunked) =================
__device__ __forceinline__ uint32_t smem_u32(const void* p) {
    uint32_t a;
    asm("{ .reg .u64 t; cvta.to.shared.u64 t, %1; cvt.u32.u64 %0, t; }" : "=r"(a) : "l"(p));
    return a;
}

#define MMA16816(d, a, b)                                                     \
    asm volatile(                                                             \
        "mma.sync.aligned.m16n8k16.row.col.f32.f16.f16.f32 "                  \
        "{%0,%1,%2,%3}, {%4,%5,%6,%7}, {%8,%9}, {%0,%1,%2,%3};"               \
        : "+f"(d[0]), "+f"(d[1]), "+f"(d[2]), "+f"(d[3])                      \
        : "r"(a[0]), "r"(a[1]), "r"(a[2]), "r"(a[3]), "r"(b[0]), "r"(b[1]))

#define LDSM4(R, ADDR)                                                        \
    asm volatile("ldmatrix.sync.aligned.m8n8.x4.shared.b16 {%0,%1,%2,%3}, [%4];" \
                 : "=r"((R)[0]), "=r"((R)[1]), "=r"((R)[2]), "=r"((R)[3])     \
                 : "r"(ADDR))

// Out[n,j] = sum_k A[n,k]*B[j,k] + bias[j] -> Cmat[n*ldc + j]; A,B interleaved (hi,lo).
__global__ void __launch_bounds__(256) gemm_mma(
    const __half2* __restrict__ A, const __half2* __restrict__ B,
    const float* __restrict__ bias, float* __restrict__ Cmat, int ldc,
    int Nr, int K, int J) {
    extern __shared__ __half sm[];
    const int KC = (K > 128) ? 128 : K;
    const int Kp = KC + 8;
    const int tsz = 128 * Kp;
    const int tid = threadIdx.x;
    const int row0 = blockIdx.y * 128, col0 = blockIdx.x * 128;

    const int warp = tid >> 5, lane = tid & 31;
    const int wm = warp >> 2, wn = warp & 3;
    const int q = lane >> 3, rr = lane & 7;
    const int g = lane >> 2, t2 = (lane & 3) * 2;

    uint32_t aHb[4], aLb[4], bHb[2], bLb[2];
    {
        const uint32_t base = smem_u32(sm);
        const int arow = wm * 64 + ((q & 1) << 3) + rr;
        const int akoff = (q >> 1) << 3;
#pragma unroll
        for (int mt = 0; mt < 4; mt++) {
            uint32_t off = (uint32_t)(((arow + mt * 16) * Kp + akoff) * 2);
            aHb[mt] = base + off;
            aLb[mt] = base + (uint32_t)(tsz * 2) + off;
        }
        const int brow = wn * 32 + ((q >> 1) << 3) + rr;
        const int bkoff = (q & 1) << 3;
#pragma unroll
        for (int nt2 = 0; nt2 < 2; nt2++) {
            uint32_t off = (uint32_t)(((brow + nt2 * 16) * Kp + bkoff) * 2);
            bHb[nt2] = base + (uint32_t)(tsz * 4) + off;
            bLb[nt2] = base + (uint32_t)(tsz * 6) + off;
        }
    }

    float acc[4][4][4];
#pragma unroll
    for (int mt = 0; mt < 4; mt++)
#pragma unroll
        for (int nt = 0; nt < 4; nt++)
#pragma unroll
            for (int e = 0; e < 4; e++) acc[mt][nt][e] = 0.f;

    const int cpr = KC >> 2;
    const int tot = 128 * cpr;
    for (int kc = 0; kc < K; kc += KC) {
#pragma unroll 1
        for (int t = 0; t < 2; t++) {
            const __half2* src = (t == 0) ? A : B;
            const int bound = (t == 0) ? Nr : J;
            const int base = (t == 0) ? row0 : col0;
            __half* hplane = sm + 2 * t * tsz;
            __half* lplane = sm + (2 * t + 1) * tsz;
            for (int i = tid; i < tot; i += 256) {
                int r = i / cpr, c = (i - r * cpr) << 2;
                int gr = base + r;
                uint4 v = make_uint4(0u, 0u, 0u, 0u);
                if (gr < bound) v = *(const uint4*)(src + (size_t)gr * K + kc + c);
                uint32_t h01 = __byte_perm(v.x, v.y, 0x5410);
                uint32_t l01 = __byte_perm(v.x, v.y, 0x7632);
                uint32_t h23 = __byte_perm(v.z, v.w, 0x5410);
                uint32_t l23 = __byte_perm(v.z, v.w, 0x7632);
                *(uint2*)(hplane + r * Kp + c) = make_uint2(h01, h23);
                *(uint2*)(lplane + r * Kp + c) = make_uint2(l01, l23);
            }
        }
        __syncthreads();
#pragma unroll 2
        for (int kt = 0; kt < KC; kt += 16) {
            const uint32_t kb = (uint32_t)(kt * 2);
            uint32_t ah[4][4], al[4][4], bh[4][2], bl[4][2];
#pragma unroll
            for (int mt = 0; mt < 4; mt++) {
                LDSM4(ah[mt], aHb[mt] + kb);
                LDSM4(al[mt], aLb[mt] + kb);
            }
#pragma unroll
            for (int nt2 = 0; nt2 < 2; nt2++) {
                uint32_t rb[4];
                LDSM4(rb, bHb[nt2] + kb);
                bh[nt2 * 2][0] = rb[0]; bh[nt2 * 2][1] = rb[1];
                bh[nt2 * 2 + 1][0] = rb[2]; bh[nt2 * 2 + 1][1] = rb[3];
                LDSM4(rb, bLb[nt2] + kb);
                bl[nt2 * 2][0] = rb[0]; bl[nt2 * 2][1] = rb[1];
                bl[nt2 * 2 + 1][0] = rb[2]; bl[nt2 * 2 + 1][1] = rb[3];
            }
#pragma unroll
            for (int mt = 0; mt < 4; mt++)
#pragma unroll
                for (int nt = 0; nt < 4; nt++) {
                    MMA16816(acc[mt][nt], ah[mt], bh[nt]);
                    MMA16816(acc[mt][nt], ah[mt], bl[nt]);
                    MMA16816(acc[mt][nt], al[mt], bh[nt]);
                }
        }
        __syncthreads();
    }

#pragma unroll
    for (int mt = 0; mt < 4; mt++) {
        int r0 = row0 + wm * 64 + mt * 16 + g;
#pragma unroll
        for (int nt = 0; nt < 4; nt++) {
            int c = col0 + wn * 32 + nt * 8 + t2;
            if (c < J) {
                float2 bv = *(const float2*)(bias + c);
                if (r0 < Nr) {
                    float2 v = make_float2(acc[mt][nt][0] + bv.x, acc[mt][nt][1] + bv.y);
                    *(float2*)(Cmat + (size_t)r0 * ldc + c) = v;
                }
                if (r0 + 8 < Nr) {
                    float2 v = make_float2(acc[mt][nt][2] + bv.x, acc[mt][nt][3] + bv.y);
                    *(float2*)(Cmat + (size_t)(r0 + 8) * ldc + c) = v;
                }
            }
        }
    }
}

// ---------------- CSR gather: aggx[w] = sum m[src] over x cols; vectorized 16B loads ----------------
// AX rows [aggx(C) | x(C)], stride 2C; reads x cols, writes aggx cols.
template <int VEC>   // VEC half2 per lane; C = VEC*32
__global__ void __launch_bounds__(256) agg_kernel(__half2* __restrict__ ax, int N) {
    const int C = VEC * 32, S = 2 * C;
    const int w = (blockIdx.x * 256 + threadIdx.x) >> 5;
    if (w >= N) return;
    const int lane = threadIdx.x & 31;
    const int e0 = g_off[w], e1 = g_off[w + 1];
    const __half2* xb = ax + C + lane * VEC;   // x-col base within row
    float acc[VEC];
#pragma unroll
    for (int i = 0; i < VEC; i++) acc[i] = 0.f;

    int e = e0;
    for (; e + 2 <= e1; e += 2) {
        const __half2* p0 = xb + (size_t)g_sse[e] * S;
        const __half2* p1 = xb + (size_t)g_sse[e + 1] * S;
        if (VEC == 4) {
            uint4 v0 = *(const uint4*)p0, v1 = *(const uint4*)p1;
            acc[0] += join_u(v0.x) + join_u(v1.x);
            acc[1] += join_u(v0.y) + join_u(v1.y);
            acc[2] += join_u(v0.z) + join_u(v1.z);
            acc[3] += join_u(v0.w) + join_u(v1.w);
        } else if (VEC == 2) {
            uint2 v0 = *(const uint2*)p0, v1 = *(const uint2*)p1;
            acc[0] += join_u(v0.x) + join_u(v1.x);
            acc[1] += join_u(v0.y) + join_u(v1.y);
        } else {
            acc[0] += join_u(*(const uint32_t*)p0) + join_u(*(const uint32_t*)p1);
        }
    }
    if (e < e1) {
        const __half2* p0 = xb + (size_t)g_sse[e] * S;
        if (VEC == 4) {
            uint4 v0 = *(const uint4*)p0;
            acc[0] += join_u(v0.x); acc[1] += join_u(v0.y);
            acc[2] += join_u(v0.z); acc[3] += join_u(v0.w);
        } else if (VEC == 2) {
            uint2 v0 = *(const uint2*)p0;
            acc[0] += join_u(v0.x); acc[1] += join_u(v0.y);
        } else {
            acc[0] += join_u(*(const uint32_t*)p0);
        }
    }

    __half2 o[VEC];
#pragma unroll
    for (int i = 0; i < VEC; i++) o[i] = split_hl(acc[i]);
    __half2* dst = ax + (size_t)w * S + lane * VEC;
    if (VEC == 4) *(uint4*)dst = *(uint4*)o;
    else if (VEC == 2) *(uint2*)dst = *(uint2*)o;
    else *dst = o[0];
}

// ---------------- GRU: x = (1-z)*tanh(in + r*hn) + z*x ; gates pre-summed ----------------
__global__ void gru_kernel(const float* __restrict__ G, __half2* __restrict__ ax,
                           int N, int C) {
    const int cq = C >> 2, C4 = 4 * C, S = 2 * C;
    long long idx = (long long)blockIdx.x * blockDim.x + threadIdx.x;
    if (idx >= (long long)N * cq) return;
    int n = (int)(idx / cq);
    int j = (int)(idx - (long long)n * cq) << 2;
    const float* row = G + (size_t)n * C4 + j;
    float4 rs = *(const float4*)(row);
    float4 zs = *(const float4*)(row + C);
    float4 in_ = *(const float4*)(row + 2 * C);
    float4 hn = *(const float4*)(row + 3 * C);
    __half2* xp = ax + (size_t)n * S + C + j;
    uint4 xv = *(uint4*)xp;
    float xo[4] = {join_u(xv.x), join_u(xv.y), join_u(xv.z), join_u(xv.w)};
    float out[4];
#define GRU1(i, f)                                                     \
    {                                                                  \
        float rr = 1.f / (1.f + expf(-rs.f));                          \
        float zz = 1.f / (1.f + expf(-zs.f));                          \
        float nn = tanhf(in_.f + rr * hn.f);                           \
        out[i] = (1.f - zz) * nn + zz * xo[i];                         \
    }
    GRU1(0, x) GRU1(1, y) GRU1(2, z) GRU1(3, w)
#undef GRU1
    __half2 o[4];
#pragma unroll
    for (int i = 0; i < 4; i++) o[i] = split_hl(out[i]);
    *(uint4*)xp = *(uint4*)o;
}

// ---------------- ELU (+optional BN) + pad; AX(x cols) -> AY(x cols) ----------------
__global__ void transition_kernel(const __half2* __restrict__ in, __half2* __restrict__ out,
                                  int N, int Cin, int Cout,
                                  const float* __restrict__ gamma,
                                  const float* __restrict__ beta,
                                  const float* __restrict__ mean,
                                  const float* __restrict__ var) {
    long long idx = (long long)blockIdx.x * blockDim.x + threadIdx.x;
    if (idx >= (long long)N * Cout) return;
    int n = (int)(idx / Cout);
    int j = (int)(idx - (long long)n * Cout);
    float v = 0.f;
    if (j < Cin) {
        v = join_hl(in[(size_t)n * 2 * Cin + Cin + j]);
        v = (v > 0.f) ? v : expm1f(v);
        if (gamma) v = (v - mean[j]) * rsqrtf(var[j] + 1e-5f) * gamma[j] + beta[j];
    }
    out[(size_t)n * 2 * Cout + Cout + j] = split_hl(v);
}

// ---------------- global add pool (reads AX x cols, C=128) ----------------
__global__ void pool_kernel(const __half2* __restrict__ ax, float* __restrict__ pool, int N) {
    long long idx = (long long)blockIdx.x * blockDim.x + threadIdx.x;
    if (idx >= (long long)N * 128) return;
    int n = (int)(idx >> 7);
    int c = (int)(idx & 127);
    atomicAdd(&pool[g_b32[n] * 128 + c], join_hl(ax[(size_t)n * 256 + 128 + c]));
}

// ---------------- SIMT GEMM for tiny fc1 ----------------
__global__ void __launch_bounds__(256, 2) gemm128(
    const float* __restrict__ A, const float* __restrict__ B,
    const float* __restrict__ bias, float* __restrict__ Cmat,
    int N, int K, int J, int act) {
    __shared__ float As[2][16][128];
    __shared__ float Bs[2][16][128];
    const int tid = threadIdx.x;
    const int tx = tid & 15, ty = tid >> 4;
    const int row0 = blockIdx.y * 128, col0 = blockIdx.x * 128;
    const int ar = tid >> 2, af = (tid & 3) << 2;
    const int bk = tid >> 5, bc = (tid & 31) << 2;

    float acc[8][8];
#pragma unroll
    for (int i = 0; i < 8; i++)
#pragma unroll
        for (int j = 0; j < 8; j++) acc[i][j] = 0.f;
    const int nk = K >> 4;
    {
#pragma unroll
        for (int h = 0; h < 2; h++) {
            int rrr = row0 + ar + h * 64;
            float4 v = make_float4(0.f, 0.f, 0.f, 0.f);
            if (rrr < N) v = *(const float4*)(A + (size_t)rrr * K + af);
            As[0][af + 0][ar + h * 64] = v.x;
            As[0][af + 1][ar + h * 64] = v.y;
            As[0][af + 2][ar + h * 64] = v.z;
            As[0][af + 3][ar + h * 64] = v.w;
        }
#pragma unroll
        for (int h = 0; h < 2; h++) {
            int k = bk + h * 8, c = col0 + bc;
            float4 v = make_float4(0.f, 0.f, 0.f, 0.f);
            if (c < J) v = *(const float4*)(B + (size_t)k * J + c);
            *(float4*)&Bs[0][k][bc] = v;
        }
    }
    __syncthreads();
    for (int tIt = 0; tIt < nk; tIt++) {
        int s = tIt & 1;
        if (tIt + 1 < nk) {
            int kt = (tIt + 1) << 4;
#pragma unroll
            for (int h = 0; h < 2; h++) {
                int rrr = row0 + ar + h * 64;
                float4 v = make_float4(0.f, 0.f, 0.f, 0.f);
                if (rrr < N) v = *(const float4*)(A + (size_t)rrr * K + kt + af);
                As[s ^ 1][af + 0][ar + h * 64] = v.x;
                As[s ^ 1][af + 1][ar + h * 64] = v.y;
                As[s ^ 1][af + 2][ar + h * 64] = v.z;
                As[s ^ 1][af + 3][ar + h * 64] = v.w;
            }
#pragma unroll
            for (int h = 0; h < 2; h++) {
                int k = bk + h * 8, c = col0 + bc;
                float4 v = make_float4(0.f, 0.f, 0.f, 0.f);
                if (c < J) v = *(const float4*)(B + (size_t)(kt + k) * J + c);
                *(float4*)&Bs[s ^ 1][k][bc] = v;
            }
        }
#pragma unroll
        for (int k = 0; k < 16; k++) {
            float a[8], b[8];
            *(float4*)&a[0] = *(const float4*)&As[s][k][ty * 4];
            *(float4*)&a[4] = *(const float4*)&As[s][k][64 + ty * 4];
            *(float4*)&b[0] = *(const float4*)&Bs[s][k][tx * 4];
            *(float4*)&b[4] = *(const float4*)&Bs[s][k][64 + tx * 4];
#pragma unroll
            for (int i = 0; i < 8; i++)
#pragma unroll
                for (int j = 0; j < 8; j++) acc[i][j] += a[i] * b[j];
        }
        __syncthreads();
    }
#pragma unroll
    for (int gi = 0; gi < 2; gi++)
#pragma unroll
        for (int i = 0; i < 4; i++) {
            int rrr = row0 + gi * 64 + ty * 4 + i;
            if (rrr >= N) continue;
#pragma unroll
            for (int gj = 0; gj < 2; gj++) {
                int c = col0 + gj * 64 + tx * 4;
                if (c >= J) continue;
                float4 v;
                v.x = acc[gi * 4 + i][gj * 4 + 0];
                v.y = acc[gi * 4 + i][gj * 4 + 1];
                v.z = acc[gi * 4 + i][gj * 4 + 2];
                v.w = acc[gi * 4 + i][gj * 4 + 3];
                if (bias) {
                    float4 bv = *(const float4*)(bias + c);
                    v.x += bv.x; v.y += bv.y; v.z += bv.z; v.w += bv.w;
                }
                if (act == 1) {
                    v.x = (v.x > 0.f) ? v.x : expm1f(v.x);
                    v.y = (v.y > 0.f) ? v.y : expm1f(v.y);
                    v.z = (v.z > 0.f) ? v.z : expm1f(v.z);
                    v.w = (v.w > 0.f) ? v.w : expm1f(v.w);
                }
                *(float4*)(Cmat + (size_t)rrr * J + c) = v;
            }
        }
}

// ---------------- fc2 + log_softmax ----------------
__global__ void fc2_kernel(const float* __restrict__ g, const float* __restrict__ W,
                           const float* __restrict__ b, float* __restrict__ out) {
    int row = blockIdx.x;
    int lane = threadIdx.x;
    __shared__ float logits[10];
    for (int j = 0; j < 10; j++) {
        float s = 0.f;
        for (int k = lane; k < 256; k += 32) s += g[row * 256 + k] * W[j * 256 + k];
#pragma unroll
        for (int o = 16; o > 0; o >>= 1) s += __shfl_down_sync(0xffffffffu, s, o);
        if (lane == 0) logits[j] = s + b[j];
    }
    __syncthreads();
    if (lane == 0) {
        float mx = logits[0];
        for (int j = 1; j < 10; j++) mx = fmaxf(mx, logits[j]);
        float se = 0.f;
        for (int j = 0; j < 10; j++) se += expf(logits[j] - mx);
        float lse = mx + logf(se);
        for (int j = 0; j < 10; j++) out[row * 10 + j] = logits[j] - lse;
    }
}

static inline int ceildiv(int a, int b) { return (a + b - 1) / b; }

extern "C" void kernel_launch(void* const* d_in, const int* in_sizes, int n_in,
                              void* d_out, int out_size) {
    const float* x_in  = (const float*)d_in[0];
    const void*  ei    = d_in[1];
    const void*  batch = d_in[2];
    const float* fc1W  = (const float*)d_in[3];
    const float* fc1b  = (const float*)d_in[4];
    const float* fc2W  = (const float*)d_in[5];
    const float* fc2b  = (const float*)d_in[6];
    const float* cW[3]   = {(const float*)d_in[7],  (const float*)d_in[12], (const float*)d_in[17]};
    const float* cwih[3] = {(const float*)d_in[8],  (const float*)d_in[13], (const float*)d_in[18]};
    const float* cwhh[3] = {(const float*)d_in[9],  (const float*)d_in[14], (const float*)d_in[19]};
    const float* cbih[3] = {(const float*)d_in[10], (const float*)d_in[15], (const float*)d_in[20]};
    const float* cbhh[3] = {(const float*)d_in[11], (const float*)d_in[16], (const float*)d_in[21]};
    const float* bng[2]  = {(const float*)d_in[22], (const float*)d_in[26]};
    const float* bnb[2]  = {(const float*)d_in[23], (const float*)d_in[27]};
    const float* bnm[2]  = {(const float*)d_in[24], (const float*)d_in[28]};
    const float* bnv[2]  = {(const float*)d_in[25], (const float*)d_in[29]};

    const int N = in_sizes[2];
    const int E = in_sizes[1] / 2;
    const int Cs[3] = {32, 64, 128};
    const int bcOff[3] = {0, 32768, 163840};   // 4*4C*2C half2 per layer
    const int bbOff[3] = {0, 128, 384};

    float *G, *POOL, *FC1, *FC1T, *BB;
    __half2 *AX, *AY, *BC;
    cudaGetSymbolAddress((void**)&G, g_G);
    cudaGetSymbolAddress((void**)&POOL, g_POOL);
    cudaGetSymbolAddress((void**)&FC1, g_FC1);
    cudaGetSymbolAddress((void**)&FC1T, g_FC1T);
    cudaGetSymbolAddress((void**)&BB, g_BB);
    cudaGetSymbolAddress((void**)&AX, g_AX);
    cudaGetSymbolAddress((void**)&AY, g_AY);
    cudaGetSymbolAddress((void**)&BC, g_BC);

    cudaFuncSetAttribute(gemm_mma, cudaFuncAttributeMaxDynamicSharedMemorySize, 139264);

    detect_kernel<<<ceildiv(N, 256), 256>>>((const unsigned*)ei, (const unsigned*)batch, E, N);
    convert_idx<<<ceildiv(E, 256), 256>>>(ei, batch, E, N);
    scan_kernel<<<1, 1024>>>(N);
    place_kernel<<<ceildiv(E, 256), 256>>>(E);

    PrepArgs pa;
    for (int L = 0; L < 3; L++) {
        pa.W[L] = cW[L]; pa.whh[L] = cwhh[L]; pa.wih[L] = cwih[L];
        pa.bih[L] = cbih[L]; pa.bhh[L] = cbhh[L];
        pa.bc[L] = BC + bcOff[L];
        pa.bb[L] = BB + bbOff[L];
    }
    pa.fc1W = fc1W; pa.fc1T = FC1T;
    pa.x = x_in; pa.ax = AX; pa.N = N;
    prep_all<<<148, 256>>>(pa);

    __half2* cur = AX;
    __half2* nxt = AY;
    const int gy = ceildiv(N, 128);
    const int aggGrid = ceildiv(N, 8);
    for (int L = 0; L < 3; L++) {
        const int C = Cs[L];
        const int C2 = 2 * C, C4 = 4 * C;
        const int KC = (C2 > 128) ? 128 : C2;
        const int smemsz = 4 * 128 * (KC + 8) * 2;
        const dim3 gg(C4 / 128, gy);
        for (int it = 0; it < 4; it++) {
            // aggx cols of AX = gather-sum of x cols
            if (C == 128)      agg_kernel<4><<<aggGrid, 256>>>(cur, N);
            else if (C == 64)  agg_kernel<2><<<aggGrid, 256>>>(cur, N);
            else               agg_kernel<1><<<aggGrid, 256>>>(cur, N);
            // G = [aggx|x] @ Bcomb^T + bias  (one GEMM: rsum|zsum|in|hn)
            gemm_mma<<<gg, 256, smemsz>>>(
                cur, BC + bcOff[L] + (size_t)it * C4 * C2, BB + bbOff[L],
                G, C4, N, C2, C4);
            // x = GRU(G, x) in place
            long long tn = (long long)N * (C / 4);
            gru_kernel<<<(int)((tn + 255) / 256), 256>>>(G, cur, N, C);
        }
        const int Cout = (L < 2) ? Cs[L + 1] : Cs[L];
        const float* ga = (L < 2) ? bng[L] : nullptr;
        const float* be = (L < 2) ? bnb[L] : nullptr;
        const float* mn = (L < 2) ? bnm[L] : nullptr;
        const float* vr = (L < 2) ? bnv[L] : nullptr;
        long long tt = (long long)N * Cout;
        transition_kernel<<<(int)((tt + 255) / 256), 256>>>(cur, nxt, N, C, Cout, ga, be, mn, vr);
        __half2* t = cur; cur = nxt; nxt = t;
    }

    cudaMemsetAsync(POOL, 0, 256 * 128 * sizeof(float));
    pool_kernel<<<ceildiv(N * 128, 256), 256>>>(cur, POOL, N);
    gemm128<<<dim3(2, 2), 256>>>(POOL, FC1T, fc1b, FC1, 256, 128, 256, 1);
    fc2_kernel<<<256, 32>>>(FC1, fc2W, fc2b, (float*)d_out);
}

// round 11
// speedup vs baseline: 1.6408x; 1.6408x over previous
#include <cuda_runtime.h>
#include <cuda_fp16.h>
#include <math.h>
#include <stdint.h>

#define MAXN 50000
#define MAXE 800000

// ---------------- device scratch (no allocations allowed) ----------------
__device__ float g_MGH[MAXN * 512];      // [m | gh] concat, row stride 4C
__device__ float g_GI [MAXN * 384];
__device__ float g_POOL[256 * 128];
__device__ float g_FC1 [256 * 256];
__device__ float g_BCB[896];             // concat bias per layer (0.. | bhh)
__device__ float g_FC1T[128 * 256];      // fc1_W^T
__device__ int   g_src[MAXE];
__device__ int   g_dst[MAXE];
__device__ int   g_sse[MAXE];            // src sorted by dst (CSR)
__device__ int   g_cnt[MAXN];
__device__ int   g_off[MAXN + 1];
__device__ int   g_b32[MAXN];
__device__ int   g_flags[2];

// fp16 split buffers
__device__ __align__(16) __half g_XHI[MAXN * 128];
__device__ __align__(16) __half g_XLO[MAXN * 128];
__device__ __align__(16) __half g_YHI[MAXN * 128];
__device__ __align__(16) __half g_YLO[MAXN * 128];
__device__ __align__(16) __half g_AHI[MAXN * 128];
__device__ __align__(16) __half g_ALO[MAXN * 128];
__device__ __align__(16) __half g_BCHI[344064];   // concat W [J=4C, K=C] per iter per layer
__device__ __align__(16) __half g_BCLO[344064];
__device__ __align__(16) __half g_BIHHI[64512];   // wih [3C, C] per layer
__device__ __align__(16) __half g_BIHLO[64512];

// ---------------- detect dtypes + zero CSR counters ----------------
__global__ void detect_kernel(const unsigned* __restrict__ ei,
                              const unsigned* __restrict__ bat, int E, int N) {
    int i = blockIdx.x * blockDim.x + threadIdx.x;
    if (i < N) g_cnt[i] = 0;
    if (blockIdx.x == 0 && threadIdx.x == 0) {
        int e64 = 1;
        for (int k = 0; k < 64; k++)
            if (ei[2 * k + 1] != 0u) { e64 = 0; break; }
        int b64 = 1;
        int b0 = N / 2 - 64;
        for (int k = 0; k < 64; k++)
            if (bat[2 * (b0 + k) + 1] != 0u) { b64 = 0; break; }
        g_flags[0] = e64;
        g_flags[1] = b64;
    }
}

__global__ void convert_idx(const void* __restrict__ ei, const void* __restrict__ bat,
                            int E, int N) {
    int i = blockIdx.x * blockDim.x + threadIdx.x;
    if (i < N)
        g_b32[i] = g_flags[1] ? (int)((const long long*)bat)[i] : ((const int*)bat)[i];
    if (i < E) {
        int s, d;
        if (g_flags[0]) {
            const long long* p = (const long long*)ei;
            s = (int)p[i]; d = (int)p[E + i];
        } else {
            const int* p = (const int*)ei;
            s = p[i]; d = p[E + i];
        }
        g_src[i] = s;
        g_dst[i] = d;
        atomicAdd(&g_cnt[d], 1);
    }
}

// ---------------- single-block exclusive scan ----------------
__global__ void __launch_bounds__(1024) scan_kernel(int N) {
    __shared__ int wsum[32];
    __shared__ int carry;
    const int tid = threadIdx.x, lane = tid & 31, wid = tid >> 5;
    if (tid == 0) carry = 0;
    __syncthreads();
    for (int base = 0; base < N; base += 1024) {
        int i = base + tid;
        int v = (i < N) ? g_cnt[i] : 0;
        int s = v;
#pragma unroll
        for (int o = 1; o < 32; o <<= 1) {
            int t = __shfl_up_sync(0xffffffffu, s, o);
            if (lane >= o) s += t;
        }
        if (lane == 31) wsum[wid] = s;
        __syncthreads();
        if (wid == 0) {
            int w = wsum[lane];
#pragma unroll
            for (int o = 1; o < 32; o <<= 1) {
                int t = __shfl_up_sync(0xffffffffu, w, o);
                if (lane >= o) w += t;
            }
            wsum[lane] = w;
        }
        __syncthreads();
        int excl = carry + ((wid > 0) ? wsum[wid - 1] : 0) + s - v;
        if (i < N) { g_off[i] = excl; g_cnt[i] = excl; }
        __syncthreads();
        if (tid == 0) carry += wsum[31];
        __syncthreads();
    }
    if (tid == 0) g_off[N] = carry;
}

__global__ void place_kernel(int E) {
    int i = blockIdx.x * blockDim.x + threadIdx.x;
    if (i >= E) return;
    int pos = atomicAdd(&g_cnt[g_dst[i]], 1);
    g_sse[pos] = g_src[i];
}

// ---------------- fp16 split helper ----------------
__device__ __forceinline__ void split_h(float v, __half& h, __half& l) {
    h = __float2half_rn(v);
    l = __float2half_rn(v - __half2float(h));
}

// ---------------- merged weight prep + initial x split (one launch) ----------------
struct PrepArgs {
    const float* W[3]; const float* whh[3]; const float* wih[3]; const float* bhh[3];
    __half* bchi[3]; __half* bclo[3]; __half* bihhi[3]; __half* bihlo[3];
    float* bcat[3];
    const float* fc1W; float* fc1T;
    const float* x; __half* xhi; __half* xlo; int N;
};

__global__ void prep_all(PrepArgs a) {
    long long stride = (long long)gridDim.x * blockDim.x;
    long long t0 = (long long)blockIdx.x * blockDim.x + threadIdx.x;
#pragma unroll
    for (int L = 0; L < 3; L++) {
        const int C = (L == 0) ? 32 : (L == 1) ? 64 : 128;
        const int C3 = 3 * C, C4 = 4 * C;
        long long tot1 = 4LL * C4 * C;
        for (long long idx = t0; idx < tot1; idx += stride) {
            int it = (int)(idx / (C4 * C));
            int rem = (int)(idx % (C4 * C));
            int j = rem / C, k = rem % C;
            float v = (j < C) ? a.W[L][(size_t)it * C * C + (size_t)k * C + j]
                              : a.whh[L][(size_t)(j - C) * C + k];
            __half h, l; split_h(v, h, l);
            a.bchi[L][idx] = h; a.bclo[L][idx] = l;
        }
        long long tot2 = (long long)C3 * C;
        for (long long idx = t0; idx < tot2; idx += stride) {
            int j = (int)(idx / C), k = (int)(idx % C);
            float v = a.wih[L][(size_t)j * C + k];
            __half h, l; split_h(v, h, l);
            a.bihhi[L][idx] = h; a.bihlo[L][idx] = l;
        }
        for (long long idx = t0; idx < C4; idx += stride)
            a.bcat[L][idx] = (idx < C) ? 0.f : a.bhh[L][idx - C];
    }
    for (long long idx = t0; idx < 128 * 256; idx += stride) {
        int k = (int)(idx / 256), j = (int)(idx % 256);
        a.fc1T[idx] = a.fc1W[(size_t)j * 128 + k];
    }
    long long totx = (long long)a.N * 32;
    for (long long idx = t0; idx < totx; idx += stride) {
        __half h, l; split_h(a.x[idx], h, l);
        a.xhi[idx] = h; a.xlo[idx] = l;
    }
}

// ================= smem-staged fp16x3 HMMA GEMM (KC=64 chunked for occupancy) =================
__device__ __forceinline__ uint32_t smem_u32(const void* p) {
    uint32_t a;
    asm("{ .reg .u64 t; cvta.to.shared.u64 t, %1; cvt.u32.u64 %0, t; }" : "=r"(a) : "l"(p));
    return a;
}

#define MMA16816(d, a, b)                                                     \
    asm volatile(                                                             \
        "mma.sync.aligned.m16n8k16.row.col.f32.f16.f16.f32 "                  \
        "{%0,%1,%2,%3}, {%4,%5,%6,%7}, {%8,%9}, {%0,%1,%2,%3};"               \
        : "+f"(d[0]), "+f"(d[1]), "+f"(d[2]), "+f"(d[3])                      \
        : "r"(a[0]), "r"(a[1]), "r"(a[2]), "r"(a[3]), "r"(b[0]), "r"(b[1]))

#define LDSM4(R, ADDR)                                                        \
    asm volatile("ldmatrix.sync.aligned.m8n8.x4.shared.b16 {%0,%1,%2,%3}, [%4];" \
                 : "=r"((R)[0]), "=r"((R)[1]), "=r"((R)[2]), "=r"((R)[3])     \
                 : "r"(ADDR))

__global__ void __launch_bounds__(256) gemm_mma(
    const __half* __restrict__ Ahi, const __half* __restrict__ Alo,
    const __half* __restrict__ Bhi, const __half* __restrict__ Blo,
    const float* __restrict__ bias, float* __restrict__ Cmat,
    int Nr, int K, int J) {
    extern __shared__ __half sm[];
    const int KC = (K > 64) ? 64 : K;     // chunk K so smem <= 73.7KB -> 2-3 CTAs/SM
    const int Kp = KC + 8;
    const int tsz = 128 * Kp;
    const int tid = threadIdx.x;
    const int row0 = blockIdx.y * 128, col0 = blockIdx.x * 128;

    const int warp = tid >> 5, lane = tid & 31;
    const int wm = warp >> 2, wn = warp & 3;
    const int q = lane >> 3, rr = lane & 7;
    const int g = lane >> 2, t2 = (lane & 3) * 2;

    // ldmatrix lane base addresses (chunk-invariant)
    uint32_t aHb[4], aLb[4], bHb[2], bLb[2];
    {
        const uint32_t base = smem_u32(sm);
        const int arow = wm * 64 + ((q & 1) << 3) + rr;
        const int akoff = (q >> 1) << 3;
#pragma unroll
        for (int mt = 0; mt < 4; mt++) {
            uint32_t off = (uint32_t)(((arow + mt * 16) * Kp + akoff) * 2);
            aHb[mt] = base + off;
            aLb[mt] = base + (uint32_t)(tsz * 2) + off;
        }
        const int brow = wn * 32 + ((q >> 1) << 3) + rr;
        const int bkoff = (q & 1) << 3;
#pragma unroll
        for (int nt2 = 0; nt2 < 2; nt2++) {
            uint32_t off = (uint32_t)(((brow + nt2 * 16) * Kp + bkoff) * 2);
            bHb[nt2] = base + (uint32_t)(tsz * 4) + off;
            bLb[nt2] = base + (uint32_t)(tsz * 6) + off;
        }
    }

    float acc[4][4][4];
#pragma unroll
    for (int mt = 0; mt < 4; mt++)
#pragma unroll
        for (int nt = 0; nt < 4; nt++)
#pragma unroll
            for (int e = 0; e < 4; e++) acc[mt][nt][e] = 0.f;

    const int cpr = KC >> 3;              // 16B chunks per staged row
    const int tot = 128 * cpr;
    for (int kc = 0; kc < K; kc += KC) {
        // ---- stage tiles for this K-chunk ----
        for (int i = tid; i < tot; i += 256) {
            int r = i / cpr, c = (i - r * cpr) << 3;
            int gr = row0 + r;
            uint4 vh = make_uint4(0u, 0u, 0u, 0u), vl = vh;
            if (gr < Nr) {
                vh = *(const uint4*)(Ahi + (size_t)gr * K + kc + c);
                vl = *(const uint4*)(Alo + (size_t)gr * K + kc + c);
            }
            *(uint4*)(sm + r * Kp + c) = vh;
            *(uint4*)(sm + tsz + r * Kp + c) = vl;
        }
        for (int i = tid; i < tot; i += 256) {
            int r = i / cpr, c = (i - r * cpr) << 3;
            int gc = col0 + r;
            uint4 vh = make_uint4(0u, 0u, 0u, 0u), vl = vh;
            if (gc < J) {
                vh = *(const uint4*)(Bhi + (size_t)gc * K + kc + c);
                vl = *(const uint4*)(Blo + (size_t)gc * K + kc + c);
            }
            *(uint4*)(sm + 2 * tsz + r * Kp + c) = vh;
            *(uint4*)(sm + 3 * tsz + r * Kp + c) = vl;
        }
        __syncthreads();

#pragma unroll 2
        for (int kt = 0; kt < KC; kt += 16) {
            const uint32_t kb = (uint32_t)(kt * 2);
            uint32_t ah[4][4], al[4][4], bh[4][2], bl[4][2];
#pragma unroll
            for (int mt = 0; mt < 4; mt++) {
                LDSM4(ah[mt], aHb[mt] + kb);
                LDSM4(al[mt], aLb[mt] + kb);
            }
#pragma unroll
            for (int nt2 = 0; nt2 < 2; nt2++) {
                uint32_t rb[4];
                LDSM4(rb, bHb[nt2] + kb);
                bh[nt2 * 2][0] = rb[0]; bh[nt2 * 2][1] = rb[1];
                bh[nt2 * 2 + 1][0] = rb[2]; bh[nt2 * 2 + 1][1] = rb[3];
                LDSM4(rb, bLb[nt2] + kb);
                bl[nt2 * 2][0] = rb[0]; bl[nt2 * 2][1] = rb[1];
                bl[nt2 * 2 + 1][0] = rb[2]; bl[nt2 * 2 + 1][1] = rb[3];
            }
#pragma unroll
            for (int mt = 0; mt < 4; mt++)
#pragma unroll
                for (int nt = 0; nt < 4; nt++) {
                    MMA16816(acc[mt][nt], ah[mt], bh[nt]);
                    MMA16816(acc[mt][nt], ah[mt], bl[nt]);
                    MMA16816(acc[mt][nt], al[mt], bh[nt]);
                }
        }
        __syncthreads();
    }

#pragma unroll
    for (int mt = 0; mt < 4; mt++) {
        int r0 = row0 + wm * 64 + mt * 16 + g;
#pragma unroll
        for (int nt = 0; nt < 4; nt++) {
            int c = col0 + wn * 32 + nt * 8 + t2;
            if (c < J) {
                float2 bv = *(const float2*)(bias + c);
                if (r0 < Nr) {
                    float2 v = make_float2(acc[mt][nt][0] + bv.x, acc[mt][nt][1] + bv.y);
                    *(float2*)(Cmat + (size_t)r0 * J + c) = v;
                }
                if (r0 + 8 < Nr) {
                    float2 v = make_float2(acc[mt][nt][2] + bv.x, acc[mt][nt][3] + bv.y);
                    *(float2*)(Cmat + (size_t)(r0 + 8) * J + c) = v;
                }
            }
        }
    }
}

// ---------------- CSR gather aggregation: agg[n] = sum_{e in in(n)} m[src[e]] ----------------
// One warp per node; float4 gathers from fp32 m; writes fp16 hi/lo splits (no atomics).
template <int VEC>
__global__ void __launch_bounds__(256) agg_kernel(
    const float* __restrict__ m, int mstride,
    __half* __restrict__ ahi, __half* __restrict__ alo, int N) {
    const int C = VEC * 32;
    const int w = (blockIdx.x * 256 + threadIdx.x) >> 5;
    if (w >= N) return;
    const int lane = threadIdx.x & 31;
    const int e0 = g_off[w], e1 = g_off[w + 1];
    float acc[VEC];
#pragma unroll
    for (int i = 0; i < VEC; i++) acc[i] = 0.f;

    int e = e0;
    for (; e + 2 <= e1; e += 2) {
        const float* r0 = m + (size_t)g_sse[e] * mstride + lane * VEC;
        const float* r1 = m + (size_t)g_sse[e + 1] * mstride + lane * VEC;
        if (VEC == 4) {
            float4 v0 = *(const float4*)r0;
            float4 v1 = *(const float4*)r1;
            acc[0] += v0.x + v1.x; acc[1] += v0.y + v1.y;
            acc[2] += v0.z + v1.z; acc[3] += v0.w + v1.w;
        } else if (VEC == 2) {
            float2 v0 = *(const float2*)r0;
            float2 v1 = *(const float2*)r1;
            acc[0] += v0.x + v1.x; acc[1] += v0.y + v1.y;
        } else {
            acc[0] += *r0 + *r1;
        }
    }
    if (e < e1) {
        const float* r0 = m + (size_t)g_sse[e] * mstride + lane * VEC;
        if (VEC == 4) {
            float4 v0 = *(const float4*)r0;
            acc[0] += v0.x; acc[1] += v0.y; acc[2] += v0.z; acc[3] += v0.w;
        } else if (VEC == 2) {
            float2 v0 = *(const float2*)r0;
            acc[0] += v0.x; acc[1] += v0.y;
        } else {
            acc[0] += *r0;
        }
    }

#pragma unroll
    for (int i = 0; i < VEC; i++) {
        __half h, l; split_h(acc[i], h, l);
        ahi[(size_t)w * C + lane * VEC + i] = h;
        alo[(size_t)w * C + lane * VEC + i] = l;
    }
}

// ---------------- GRU pointwise + fp16 split of new x ----------------
__global__ void gru_kernel(float* __restrict__ x_unused, const float* __restrict__ gi,
                           const float* __restrict__ mgh,
                           __half* __restrict__ xh, __half* __restrict__ xl,
                           int N, int C) {
    const int cq = C >> 2, C3 = 3 * C, C4 = 4 * C;
    long long idx = (long long)blockIdx.x * blockDim.x + threadIdx.x;
    if (idx >= (long long)N * cq) return;
    int n = (int)(idx / cq);
    int j = (int)(idx - (long long)n * cq) << 2;
    const float* gin = gi + (size_t)n * C3 + j;
    const float* ghn = mgh + (size_t)n * C4 + C + j;
    float4 ir = *(const float4*)(gin);
    float4 iz = *(const float4*)(gin + C);
    float4 in_ = *(const float4*)(gin + 2 * C);
    float4 hr = *(const float4*)(ghn);
    float4 hz = *(const float4*)(ghn + C);
    float4 hn = *(const float4*)(ghn + 2 * C);
    __half* hp = xh + (size_t)n * C + j;
    __half* lp = xl + (size_t)n * C + j;
    // reconstruct old x from splits (exact to 2^-22)
    float xo[4];
#pragma unroll
    for (int i = 0; i < 4; i++)
        xo[i] = __half2float(hp[i]) + __half2float(lp[i]);
    float out[4];
#define GRU1(i, f)                                                     \
    {                                                                  \
        float rr = 1.f / (1.f + expf(-(ir.f + hr.f)));                 \
        float zz = 1.f / (1.f + expf(-(iz.f + hz.f)));                 \
        float nn = tanhf(in_.f + rr * hn.f);                           \
        out[i] = (1.f - zz) * nn + zz * xo[i];                         \
    }
    GRU1(0, x) GRU1(1, y) GRU1(2, z) GRU1(3, w)
#undef GRU1
#pragma unroll
    for (int i = 0; i < 4; i++) {
        __half h, l; split_h(out[i], h, l);
        hp[i] = h; lp[i] = l;
    }
}

// ---------------- ELU (+optional BN) + pad; splits -> splits ----------------
__global__ void transition_kernel(const __half* __restrict__ inh, const __half* __restrict__ inl,
                                  __half* __restrict__ outh, __half* __restrict__ outl,
                                  int N, int Cin, int Cout,
                                  const float* __restrict__ gamma,
                                  const float* __restrict__ beta,
                                  const float* __restrict__ mean,
                                  const float* __restrict__ var) {
    long long idx = (long long)blockIdx.x * blockDim.x + threadIdx.x;
    if (idx >= (long long)N * Cout) return;
    int n = (int)(idx / Cout);
    int j = (int)(idx - (long long)n * Cout);
    float v = 0.f;
    if (j < Cin) {
        size_t o = (size_t)n * Cin + j;
        v = __half2float(inh[o]) + __half2float(inl[o]);
        v = (v > 0.f) ? v : expm1f(v);
        if (gamma) v = (v - mean[j]) * rsqrtf(var[j] + 1e-5f) * gamma[j] + beta[j];
    }
    __half h, l; split_h(v, h, l);
    outh[idx] = h;
    outl[idx] = l;
}

// ---------------- global add pool (reads splits) ----------------
__global__ void pool_kernel(const __half* __restrict__ xh, const __half* __restrict__ xl,
                            float* __restrict__ pool, int N) {
    long long idx = (long long)blockIdx.x * blockDim.x + threadIdx.x;
    if (idx >= (long long)N * 128) return;
    int n = (int)(idx >> 7);
    int c = (int)(idx & 127);
    float v = __half2float(xh[idx]) + __half2float(xl[idx]);
    atomicAdd(&pool[g_b32[n] * 128 + c], v);
}

// ---------------- SIMT GEMM for tiny fc1 ----------------
__global__ void __launch_bounds__(256, 2) gemm128(
    const float* __restrict__ A, const float* __restrict__ B,
    const float* __restrict__ bias, float* __restrict__ Cmat,
    int N, int K, int J, int act) {
    __shared__ float As[2][16][128];
    __shared__ float Bs[2][16][128];
    const int tid = threadIdx.x;
    const int tx = tid & 15, ty = tid >> 4;
    const int row0 = blockIdx.y * 128, col0 = blockIdx.x * 128;
    const int ar = tid >> 2, af = (tid & 3) << 2;
    const int bk = tid >> 5, bc = (tid & 31) << 2;

    float acc[8][8];
#pragma unroll
    for (int i = 0; i < 8; i++)
#pragma unroll
        for (int j = 0; j < 8; j++) acc[i][j] = 0.f;
    const int nk = K >> 4;
    {
#pragma unroll
        for (int h = 0; h < 2; h++) {
            int rrr = row0 + ar + h * 64;
            float4 v = make_float4(0.f, 0.f, 0.f, 0.f);
            if (rrr < N) v = *(const float4*)(A + (size_t)rrr * K + af);
            As[0][af + 0][ar + h * 64] = v.x;
            As[0][af + 1][ar + h * 64] = v.y;
            As[0][af + 2][ar + h * 64] = v.z;
            As[0][af + 3][ar + h * 64] = v.w;
        }
#pragma unroll
        for (int h = 0; h < 2; h++) {
            int k = bk + h * 8, c = col0 + bc;
            float4 v = make_float4(0.f, 0.f, 0.f, 0.f);
            if (c < J) v = *(const float4*)(B + (size_t)k * J + c);
            *(float4*)&Bs[0][k][bc] = v;
        }
    }
    __syncthreads();
    for (int tIt = 0; tIt < nk; tIt++) {
        int s = tIt & 1;
        if (tIt + 1 < nk) {
            int kt = (tIt + 1) << 4;
#pragma unroll
            for (int h = 0; h < 2; h++) {
                int rrr = row0 + ar + h * 64;
                float4 v = make_float4(0.f, 0.f, 0.f, 0.f);
                if (rrr < N) v = *(const float4*)(A + (size_t)rrr * K + kt + af);
                As[s ^ 1][af + 0][ar + h * 64] = v.x;
                As[s ^ 1][af + 1][ar + h * 64] = v.y;
                As[s ^ 1][af + 2][ar + h * 64] = v.z;
                As[s ^ 1][af + 3][ar + h * 64] = v.w;
            }
#pragma unroll
            for (int h = 0; h < 2; h++) {
                int k = bk + h * 8, c = col0 + bc;
                float4 v = make_float4(0.f, 0.f, 0.f, 0.f);
                if (c < J) v = *(const float4*)(B + (size_t)(kt + k) * J + c);
                *(float4*)&Bs[s ^ 1][k][bc] = v;
            }
        }
#pragma unroll
        for (int k = 0; k < 16; k++) {
            float a[8], b[8];
            *(float4*)&a[0] = *(const float4*)&As[s][k][ty * 4];
            *(float4*)&a[4] = *(const float4*)&As[s][k][64 + ty * 4];
            *(float4*)&b[0] = *(const float4*)&Bs[s][k][tx * 4];
            *(float4*)&b[4] = *(const float4*)&Bs[s][k][64 + tx * 4];
#pragma unroll
            for (int i = 0; i < 8; i++)
#pragma unroll
                for (int j = 0; j < 8; j++) acc[i][j] += a[i] * b[j];
        }
        __syncthreads();
    }
#pragma unroll
    for (int gi = 0; gi < 2; gi++)
#pragma unroll
        for (int i = 0; i < 4; i++) {
            int rrr = row0 + gi * 64 + ty * 4 + i;
            if (rrr >= N) continue;
#pragma unroll
            for (int gj = 0; gj < 2; gj++) {
                int c = col0 + gj * 64 + tx * 4;
                if (c >= J) continue;
                float4 v;
                v.x = acc[gi * 4 + i][gj * 4 + 0];
                v.y = acc[gi * 4 + i][gj * 4 + 1];
                v.z = acc[gi * 4 + i][gj * 4 + 2];
                v.w = acc[gi * 4 + i][gj * 4 + 3];
                if (bias) {
                    float4 bv = *(const float4*)(bias + c);
                    v.x += bv.x; v.y += bv.y; v.z += bv.z; v.w += bv.w;
                }
                if (act == 1) {
                    v.x = (v.x > 0.f) ? v.x : expm1f(v.x);
                    v.y = (v.y > 0.f) ? v.y : expm1f(v.y);
                    v.z = (v.z > 0.f) ? v.z : expm1f(v.z);
                    v.w = (v.w > 0.f) ? v.w : expm1f(v.w);
                }
                *(float4*)(Cmat + (size_t)rrr * J + c) = v;
            }
        }
}

// ---------------- fc2 + log_softmax ----------------
__global__ void fc2_kernel(const float* __restrict__ g, const float* __restrict__ W,
                           const float* __restrict__ b, float* __restrict__ out) {
    int row = blockIdx.x;
    int lane = threadIdx.x;
    __shared__ float logits[10];
    for (int j = 0; j < 10; j++) {
        float s = 0.f;
        for (int k = lane; k < 256; k += 32) s += g[row * 256 + k] * W[j * 256 + k];
#pragma unroll
        for (int o = 16; o > 0; o >>= 1) s += __shfl_down_sync(0xffffffffu, s, o);
        if (lane == 0) logits[j] = s + b[j];
    }
    __syncthreads();
    if (lane == 0) {
        float mx = logits[0];
        for (int j = 1; j < 10; j++) mx = fmaxf(mx, logits[j]);
        float se = 0.f;
        for (int j = 0; j < 10; j++) se += expf(logits[j] - mx);
        float lse = mx + logf(se);
        for (int j = 0; j < 10; j++) out[row * 10 + j] = logits[j] - lse;
    }
}

static inline int ceildiv(int a, int b) { return (a + b - 1) / b; }

extern "C" void kernel_launch(void* const* d_in, const int* in_sizes, int n_in,
                              void* d_out, int out_size) {
    const float* x_in  = (const float*)d_in[0];
    const void*  ei    = d_in[1];
    const void*  batch = d_in[2];
    const float* fc1W  = (const float*)d_in[3];
    const float* fc1b  = (const float*)d_in[4];
    const float* fc2W  = (const float*)d_in[5];
    const float* fc2b  = (const float*)d_in[6];
    const float* cW[3]   = {(const float*)d_in[7],  (const float*)d_in[12], (const float*)d_in[17]};
    const float* cwih[3] = {(const float*)d_in[8],  (const float*)d_in[13], (const float*)d_in[18]};
    const float* cwhh[3] = {(const float*)d_in[9],  (const float*)d_in[14], (const float*)d_in[19]};
    const float* cbih[3] = {(const float*)d_in[10], (const float*)d_in[15], (const float*)d_in[20]};
    const float* cbhh[3] = {(const float*)d_in[11], (const float*)d_in[16], (const float*)d_in[21]};
    const float* bng[2]  = {(const float*)d_in[22], (const float*)d_in[26]};
    const float* bnb[2]  = {(const float*)d_in[23], (const float*)d_in[27]};
    const float* bnm[2]  = {(const float*)d_in[24], (const float*)d_in[28]};
    const float* bnv[2]  = {(const float*)d_in[25], (const float*)d_in[29]};

    const int N = in_sizes[2];
    const int E = in_sizes[1] / 2;
    const int Cs[3] = {32, 64, 128};
    const int bcOff[3]  = {0, 16384, 81920};
    const int bihOff[3] = {0, 3072, 15360};
    const int bbOff[3]  = {0, 128, 128 + 256};

    float *MGH, *GI, *POOL, *FC1, *BCB, *FC1T;
    __half *XHI, *XLO, *YHI, *YLO, *AHI, *ALO, *BCHI, *BCLO, *BIHHI, *BIHLO;
    cudaGetSymbolAddress((void**)&MGH, g_MGH);
    cudaGetSymbolAddress((void**)&GI, g_GI);
    cudaGetSymbolAddress((void**)&POOL, g_POOL);
    cudaGetSymbolAddress((void**)&FC1, g_FC1);
    cudaGetSymbolAddress((void**)&BCB, g_BCB);
    cudaGetSymbolAddress((void**)&FC1T, g_FC1T);
    cudaGetSymbolAddress((void**)&XHI, g_XHI);
    cudaGetSymbolAddress((void**)&XLO, g_XLO);
    cudaGetSymbolAddress((void**)&YHI, g_YHI);
    cudaGetSymbolAddress((void**)&YLO, g_YLO);
    cudaGetSymbolAddress((void**)&AHI, g_AHI);
    cudaGetSymbolAddress((void**)&ALO, g_ALO);
    cudaGetSymbolAddress((void**)&BCHI, g_BCHI);
    cudaGetSymbolAddress((void**)&BCLO, g_BCLO);
    cudaGetSymbolAddress((void**)&BIHHI, g_BIHHI);
    cudaGetSymbolAddress((void**)&BIHLO, g_BIHLO);

    // KC=64 chunking -> max smem 4*128*72*2 = 73728 B
    cudaFuncSetAttribute(gemm_mma, cudaFuncAttributeMaxDynamicSharedMemorySize, 73728);

    detect_kernel<<<ceildiv(N, 256), 256>>>((const unsigned*)ei, (const unsigned*)batch, E, N);
    convert_idx<<<ceildiv(E, 256), 256>>>(ei, batch, E, N);
    scan_kernel<<<1, 1024>>>(N);
    place_kernel<<<ceildiv(E, 256), 256>>>(E);

    PrepArgs pa;
    for (int L = 0; L < 3; L++) {
        pa.W[L] = cW[L]; pa.whh[L] = cwhh[L]; pa.wih[L] = cwih[L]; pa.bhh[L] = cbhh[L];
        pa.bchi[L] = BCHI + bcOff[L]; pa.bclo[L] = BCLO + bcOff[L];
        pa.bihhi[L] = BIHHI + bihOff[L]; pa.bihlo[L] = BIHLO + bihOff[L];
        pa.bcat[L] = BCB + bbOff[L];
    }
    pa.fc1W = fc1W; pa.fc1T = FC1T;
    pa.x = x_in; pa.xhi = XHI; pa.xlo = XLO; pa.N = N;
    prep_all<<<148, 256>>>(pa);

    __half* curH = XHI; __half* curL = XLO;
    __half* nxtH = YHI; __half* nxtL = YLO;
    const int gy = ceildiv(N, 128);
    const int aggGrid = ceildiv(N, 8);
    for (int L = 0; L < 3; L++) {
        const int C = Cs[L];
        const int C3 = 3 * C, C4 = 4 * C;
        const int KC = (C > 64) ? 64 : C;
        const int smemsz = 4 * 128 * (KC + 8) * 2;
        for (int it = 0; it < 4; it++) {
            // [m | gh] = x @ [W(it) | whh^T]  (+ [0 | bhh])
            gemm_mma<<<dim3(ceildiv(C4, 128), gy), 256, smemsz>>>(
                curH, curL, BCHI + bcOff[L] + (size_t)it * C4 * C,
                BCLO + bcOff[L] + (size_t)it * C4 * C, BCB + bbOff[L],
                MGH, N, C, C4);
            // agg = CSR gather-sum of m rows; writes fp16 hi/lo directly
            if (C == 128)      agg_kernel<4><<<aggGrid, 256>>>(MGH, C4, AHI, ALO, N);
            else if (C == 64)  agg_kernel<2><<<aggGrid, 256>>>(MGH, C4, AHI, ALO, N);
            else               agg_kernel<1><<<aggGrid, 256>>>(MGH, C4, AHI, ALO, N);
            // gi = agg @ wih^T + bih
            gemm_mma<<<dim3(ceildiv(C3, 128), gy), 256, smemsz>>>(
                AHI, ALO, BIHHI + bihOff[L], BIHLO + bihOff[L], cbih[L],
                GI, N, C, C3);
            // x = GRU(gi, gh, x); refresh fp16 split of x
            long long tn = (long long)N * (C / 4);
            gru_kernel<<<(int)((tn + 255) / 256), 256>>>(nullptr, GI, MGH, curH, curL, N, C);
        }
        const int Cout = (L < 2) ? Cs[L + 1] : Cs[L];
        const float* ga = (L < 2) ? bng[L] : nullptr;
        const float* be = (L < 2) ? bnb[L] : nullptr;
        const float* mn = (L < 2) ? bnm[L] : nullptr;
        const float* vr = (L < 2) ? bnv[L] : nullptr;
        long long tt = (long long)N * Cout;
        transition_kernel<<<(int)((tt + 255) / 256), 256>>>(curH, curL, nxtH, nxtL,
                                                            N, C, Cout, ga, be, mn, vr);
        __half* t;
        t = curH; curH = nxtH; nxtH = t;
        t = curL; curL = nxtL; nxtL = t;
    }

    cudaMemsetAsync(POOL, 0, 256 * 128 * sizeof(float));
    pool_kernel<<<ceildiv(N * 128, 256), 256>>>(curH, curL, POOL, N);
    gemm128<<<dim3(2, 2), 256>>>(POOL, FC1T, fc1b, FC1, 256, 128, 256, 1);
    fc2_kernel<<<256, 32>>>(FC1, fc2W, fc2b, (float*)d_out);
}